// round 14
// baseline (speedup 1.0000x reference)
#include <cuda_runtime.h>
#include <cuda_bf16.h>
#include <math.h>

// ---------------- problem constants ----------------
#define BB    2
#define LL    1024
#define DM    256
#define DI    512
#define DS    16
#define DR    16
#define DCV   4
#define VB    4               // 2 chains (fwd/bwd) x 2 batch, fused
#define MR2   (VB*LL)         // 4096 rows per GEMM
#define NC    32              // scan chunks
#define CH    (LL/NC)         // 32 steps per chunk
#define NXP   64              // x_proj N padded (48 -> 64)

typedef unsigned long long u64;
typedef unsigned int u32;
typedef __nv_bfloat16 bf16;

// ---------------- device scratch (no allocation allowed) ----------------
__device__ __align__(16) bf16 g_a_hi[MR2*DM],  g_a_lo[MR2*DM];    // layer-0 input split
__device__ __align__(16) bf16 g_b_hi[MR2*DM],  g_b_lo[MR2*DM];    // layer-1 input split
__device__ __align__(16) bf16 g_xc_hi[MR2*DI], g_xc_lo[MR2*DI];   // conv+silu output split
__device__ __align__(16) bf16 g_y_hi[MR2*DI],  g_y_lo[MR2*DI];    // scan output split
__device__ __align__(16) float g_xz [MR2*2*DI];   // in_proj output (xc | z) fp32
__device__ __align__(16) float g_dbl[MR2*48];     // x_proj output (dt_raw|B|C)
__device__ __align__(16) float g_dt [MR2*DI];     // softplus(dt)
__device__ __align__(16) float g_P  [VB*DI*NC*DS];
__device__ __align__(16) float g_H  [VB*DI*NC*DS];
__device__ __align__(16) float g_Hi [VB*DI*NC*DS];
// weight splits (4 layers each)
__device__ __align__(16) bf16 g_wi_hi[4*2*DI*DM], g_wi_lo[4*2*DI*DM];  // in_proj  (1024,256)
__device__ __align__(16) bf16 g_wx_hi[4*NXP*DI],  g_wx_lo[4*NXP*DI];   // x_proj   (64,512) padded
__device__ __align__(16) bf16 g_wo_hi[4*DM*DI],   g_wo_lo[4*DM*DI];    // out_proj (256,512)

// ---------------- baseline-PTX helpers (valid on compute_103) ----------------
__device__ __forceinline__ u32 smem_u32(const void* p) {
    u32 a;
    asm("{ .reg .u64 t; cvta.to.shared.u64 t, %1; cvt.u32.u64 %0, t; }" : "=r"(a) : "l"(p));
    return a;
}
__device__ __forceinline__ void ldmx4(u32& r0, u32& r1, u32& r2, u32& r3, u32 addr) {
    asm volatile("ldmatrix.sync.aligned.m8n8.x4.shared.b16 {%0,%1,%2,%3}, [%4];"
        : "=r"(r0), "=r"(r1), "=r"(r2), "=r"(r3) : "r"(addr));
}
__device__ __forceinline__ void ldmx2(u32& r0, u32& r1, u32 addr) {
    asm volatile("ldmatrix.sync.aligned.m8n8.x2.shared.b16 {%0,%1}, [%2];"
        : "=r"(r0), "=r"(r1) : "r"(addr));
}
__device__ __forceinline__ void mma16816(float* c, const u32* a, const u32* b) {
    asm volatile("mma.sync.aligned.m16n8k16.row.col.f32.bf16.bf16.f32 "
        "{%0,%1,%2,%3}, {%4,%5,%6,%7}, {%8,%9}, {%0,%1,%2,%3};"
        : "+f"(c[0]), "+f"(c[1]), "+f"(c[2]), "+f"(c[3])
        : "r"(a[0]), "r"(a[1]), "r"(a[2]), "r"(a[3]), "r"(b[0]), "r"(b[1]));
}
__device__ __forceinline__ void split2(float v, bf16& hi, bf16& lo) {
    hi = __float2bfloat16(v);
    lo = __float2bfloat16(v - __bfloat162float(hi));
}
__device__ __forceinline__ u32 packbf(bf16 a, bf16 b) {
    __nv_bfloat162 t = __halves2bfloat162(a, b);
    return *(u32*)&t;
}

// ---------------- single init kernel: weight splits + input prep ----------------
#define N_WI (4*2*DI*DM)      // 1048576
#define N_WO (4*DM*DI)        // 524288
#define N_WX (4*NXP*DI)       // 131072
#define N_PR (MR2*DM)         // 1048576
__global__ void init_k(const float* __restrict__ x, const float* __restrict__ in_proj,
                       const float* __restrict__ out_proj, const float* __restrict__ x_proj)
{
    int i = blockIdx.x*256 + threadIdx.x;
    if (i < N_WI) {
        split2(in_proj[i], g_wi_hi[i], g_wi_lo[i]);
        return;
    }
    i -= N_WI;
    if (i < N_WO) {
        split2(out_proj[i], g_wo_hi[i], g_wo_lo[i]);
        return;
    }
    i -= N_WO;
    if (i < N_WX) {
        int k = i & (DI-1);
        int n = (i >> 9) & (NXP-1);
        int lay = i >> 15;
        float v = (n < 48) ? x_proj[((size_t)lay*48 + n)*DI + k] : 0.f;
        split2(v, g_wx_hi[i], g_wx_lo[i]);
        return;
    }
    i -= N_WX;
    if (i < N_PR) {
        int m = i & (DM-1);
        int r = i >> 8;
        int l = r & (LL-1);
        int b = (r >> 10) & 1;
        int chain = r >> 11;
        int sl = chain ? (LL-1-l) : l;
        split2(x[(size_t)(b*LL + sl)*DM + m], g_a_hi[i], g_a_lo[i]);
    }
}

// ---------------- HMMA GEMM (R8 single-buffer version) ----------------
// C[m,n] = sum_k A[m,k]*W[n,k], bf16 hi/lo split (3 products). BN fixed 64.
// MODE 0: fp32 store (Nvalid mask). MODE 1: final interleaved/reversed out.
// MODE 2: hi/lo split bf16 store. Rows >= 2048 use (Whi1,Wlo1).
template<int BM, int MODE>
__global__ __launch_bounds__(256)
void gemm_mma(const bf16* __restrict__ Ahi, const bf16* __restrict__ Alo,
              const bf16* __restrict__ Whi0, const bf16* __restrict__ Wlo0,
              const bf16* __restrict__ Whi1, const bf16* __restrict__ Wlo1,
              float* __restrict__ Cf, bf16* __restrict__ Chi, bf16* __restrict__ Clo,
              int K, int ldc, int Nvalid)
{
    constexpr int BN = 64;
    constexpr int MT = BM/32;
    constexpr int ASZ = BM*80;
    constexpr int WSZ = BN*80;

    __shared__ __align__(16) char smA[2*ASZ];   // [hi | lo]
    __shared__ __align__(16) char smW[2*WSZ];   // [hi | lo]
    u32 sa = smem_u32(smA);
    u32 sw = smem_u32(smW);

    int tid  = threadIdx.x;
    int lane = tid & 31;
    int wid  = tid >> 5;
    int wm   = wid & 1;
    int wn   = wid >> 1;
    int m0   = blockIdx.y * BM;
    int n0   = blockIdx.x * BN;

    const bf16* __restrict__ Whi = (m0 >= MR2/2) ? Whi1 : Whi0;
    const bf16* __restrict__ Wlo = (m0 >= MR2/2) ? Wlo1 : Wlo0;

    float acc[MT][2][4];
#pragma unroll
    for (int mt = 0; mt < MT; mt++)
#pragma unroll
        for (int nt = 0; nt < 2; nt++)
#pragma unroll
            for (int r = 0; r < 4; r++) acc[mt][nt][r] = 0.f;

    const int NCH = K >> 5;

    for (int c = 0; c < NCH; c++) {
        int kt = c << 5;
        __syncthreads();
#pragma unroll
        for (int i = tid; i < BM*4; i += 256) {
            int m = i >> 2, seg = i & 3;
            size_t go = (size_t)(m0 + m)*K + kt + seg*8;
            int so = m*80 + seg*16;
            *(uint4*)(smA + so)       = *(const uint4*)(Ahi + go);
            *(uint4*)(smA + ASZ + so) = *(const uint4*)(Alo + go);
        }
        for (int i = tid; i < BN*4; i += 256) {
            int n = i >> 2, seg = i & 3;
            size_t go = (size_t)(n0 + n)*K + kt + seg*8;
            int so = n*80 + seg*16;
            *(uint4*)(smW + so)       = *(const uint4*)(Whi + go);
            *(uint4*)(smW + WSZ + so) = *(const uint4*)(Wlo + go);
        }
        __syncthreads();

#pragma unroll
        for (int ksb = 0; ksb < 2; ksb++) {
            int kb = ksb*32;
            u32 ah[MT][4], al[MT][4];
#pragma unroll
            for (int mt = 0; mt < MT; mt++) {
                u32 addr = sa + (wm*(BM/2) + mt*16 + (lane & 15))*80 + kb + ((lane >> 4) << 4);
                ldmx4(ah[mt][0], ah[mt][1], ah[mt][2], ah[mt][3], addr);
                ldmx4(al[mt][0], al[mt][1], al[mt][2], al[mt][3], addr + ASZ);
            }
            u32 bh[2][2], bl[2][2];
#pragma unroll
            for (int nt = 0; nt < 2; nt++) {
                u32 addr = sw + (wn*16 + nt*8 + (lane & 7))*80 + kb + (((lane >> 3) & 1) << 4);
                ldmx2(bh[nt][0], bh[nt][1], addr);
                ldmx2(bl[nt][0], bl[nt][1], addr + WSZ);
            }
#pragma unroll
            for (int mt = 0; mt < MT; mt++)
#pragma unroll
                for (int nt = 0; nt < 2; nt++) {
                    mma16816(acc[mt][nt], ah[mt], bh[nt]);
                    mma16816(acc[mt][nt], ah[mt], bl[nt]);
                    mma16816(acc[mt][nt], al[mt], bh[nt]);
                }
        }
    }

#pragma unroll
    for (int mt = 0; mt < MT; mt++) {
        int mrow = m0 + wm*(BM/2) + mt*16 + (lane >> 2);
#pragma unroll
        for (int nt = 0; nt < 2; nt++) {
            int n = n0 + wn*16 + nt*8 + 2*(lane & 3);
            float* a = acc[mt][nt];
            if constexpr (MODE == 0) {
                if (n < Nvalid) {
                    *(float2*)&Cf[(size_t)mrow*ldc + n]     = make_float2(a[0], a[1]);
                    *(float2*)&Cf[(size_t)(mrow+8)*ldc + n] = make_float2(a[2], a[3]);
                }
            } else if constexpr (MODE == 1) {
#pragma unroll
                for (int rr = 0; rr < 2; rr++) {
                    int m = mrow + rr*8;
                    int chain = m >> 11, bb = (m >> 10) & 1, l = m & (LL-1);
                    int dr = bb*LL + (chain ? (LL-1-l) : l);
                    *(float2*)&Cf[(size_t)dr*ldc + chain*DM + n] = make_float2(a[rr*2], a[rr*2+1]);
                }
            } else {
#pragma unroll
                for (int rr = 0; rr < 2; rr++) {
                    size_t o = (size_t)(mrow + rr*8)*ldc + n;
                    bf16 h0, l0, h1, l1;
                    split2(a[rr*2],   h0, l0);
                    split2(a[rr*2+1], h1, l1);
                    *(u32*)&Chi[o] = packbf(h0, h1);
                    *(u32*)&Clo[o] = packbf(l0, l1);
                }
            }
        }
    }
}

// ---------------- x_proj GEMM with fused conv+silu A producer ----------------
// Computes xc = silu(causal_conv(g_xz)) on the fly per A tile (grid.x == 1 so each A
// element is produced exactly once), writes xc_hi/lo to global for the scans, and
// runs the bf16-split MMA against the padded x_proj weights. Output g_dbl (N=48).
__global__ __launch_bounds__(256)
void xproj_k(const float* __restrict__ cw0, const float* __restrict__ cw1,
             const float* __restrict__ cb0, const float* __restrict__ cb1,
             const bf16* __restrict__ Whi0, const bf16* __restrict__ Wlo0,
             const bf16* __restrict__ Whi1, const bf16* __restrict__ Wlo1)
{
    constexpr int BM = 32, BN = 64;
    constexpr int ASZ = BM*80;
    constexpr int WSZ = BN*80;

    __shared__ __align__(16) char smA[2*ASZ];
    __shared__ __align__(16) char smW[2*WSZ];
    u32 sa = smem_u32(smA);
    u32 sw = smem_u32(smW);

    int tid  = threadIdx.x;
    int lane = tid & 31;
    int wid  = tid >> 5;
    int wm   = wid & 1;
    int wn   = wid >> 1;
    int m0   = blockIdx.y * BM;
    int chain = (m0 >= MR2/2) ? 1 : 0;

    const float* __restrict__ cw = chain ? cw1 : cw0;
    const float* __restrict__ cb = chain ? cb1 : cb0;
    const bf16* __restrict__ Whi = chain ? Whi1 : Whi0;
    const bf16* __restrict__ Wlo = chain ? Wlo1 : Wlo0;

    float acc[2][4];
#pragma unroll
    for (int nt = 0; nt < 2; nt++)
#pragma unroll
        for (int r = 0; r < 4; r++) acc[nt][r] = 0.f;

    // this thread's fixed d-lane within each 32-wide chunk
    int dd = tid & 31;
    int r0 = tid >> 5;          // row group 0..7

    const int NCH = DI >> 5;    // 16 chunks
    for (int c = 0; c < NCH; c++) {
        int kt = c << 5;
        int d  = kt + dd;
        // conv params for this d
        float c0 = cw[d*DCV+0], c1 = cw[d*DCV+1], c2 = cw[d*DCV+2], c3 = cw[d*DCV+3];
        float bv = cb[d];

        __syncthreads();
        // A tile: compute conv+silu for 32 rows x 32 d, write smem + global xc
#pragma unroll
        for (int rr = 0; rr < 4; rr++) {
            int row = r0 + rr*8;            // 0..31
            int gr  = m0 + row;
            int l   = gr & (LL-1);
            size_t base = (size_t)gr*(2*DI) + d;
            float a3 = g_xz[base];          // k=3 (current row), always valid
            float s  = fmaf(a3, c3, bv);
            if (l >= 1) s = fmaf(g_xz[base - (size_t)(2*DI)],   c2, s);
            if (l >= 2) s = fmaf(g_xz[base - (size_t)(4*DI)],   c1, s);
            if (l >= 3) s = fmaf(g_xz[base - (size_t)(6*DI)],   c0, s);
            float v = s * __fdividef(1.f, 1.f + __expf(-s));
            bf16 h, lo;
            split2(v, h, lo);
            size_t go = (size_t)gr*DI + d;
            g_xc_hi[go] = h;
            g_xc_lo[go] = lo;
            int so = row*80 + dd*2;
            *(bf16*)(smA + so)       = h;
            *(bf16*)(smA + ASZ + so) = lo;
        }
        // W tile: 64 rows x 32 d
        {
            int i = tid;                    // 256 threads, 256 uint4 per split
            int n = i >> 2, seg = i & 3;
            size_t go = (size_t)n*DI + kt + seg*8;
            int so = n*80 + seg*16;
            *(uint4*)(smW + so)       = *(const uint4*)(Whi + go);
            *(uint4*)(smW + WSZ + so) = *(const uint4*)(Wlo + go);
        }
        __syncthreads();

#pragma unroll
        for (int ksb = 0; ksb < 2; ksb++) {
            int kb = ksb*32;
            u32 ah[4], al[4];
            {
                u32 addr = sa + (wm*16 + (lane & 15))*80 + kb + ((lane >> 4) << 4);
                ldmx4(ah[0], ah[1], ah[2], ah[3], addr);
                ldmx4(al[0], al[1], al[2], al[3], addr + ASZ);
            }
            u32 bh[2][2], bl[2][2];
#pragma unroll
            for (int nt = 0; nt < 2; nt++) {
                u32 addr = sw + (wn*16 + nt*8 + (lane & 7))*80 + kb + (((lane >> 3) & 1) << 4);
                ldmx2(bh[nt][0], bh[nt][1], addr);
                ldmx2(bl[nt][0], bl[nt][1], addr + WSZ);
            }
#pragma unroll
            for (int nt = 0; nt < 2; nt++) {
                mma16816(acc[nt], ah, bh[nt]);
                mma16816(acc[nt], ah, bl[nt]);
                mma16816(acc[nt], al, bh[nt]);
            }
        }
    }

    // epilogue -> g_dbl (ldc=48, Nvalid=48)
    int mrow = m0 + wm*16 + (lane >> 2);
#pragma unroll
    for (int nt = 0; nt < 2; nt++) {
        int n = wn*16 + nt*8 + 2*(lane & 3);
        float* a = acc[nt];
        if (n < 48) {
            *(float2*)&g_dbl[(size_t)mrow*48 + n]     = make_float2(a[0], a[1]);
            *(float2*)&g_dbl[(size_t)(mrow+8)*48 + n] = make_float2(a[2], a[3]);
        }
    }
}

// ---------------- scan pass 1: fused dt + per-chunk products/local states ----------------
__global__ __launch_bounds__(128)
void scan1_k(const float* __restrict__ Al0, const float* __restrict__ Al1,
             const float* __restrict__ Wdt0, const float* __restrict__ Wdt1,
             const float* __restrict__ bdt0, const float* __restrict__ bdt1)
{
    __shared__ float Bsm[CH][DS];
    __shared__ float Dsm[CH][DR];
    int tid = threadIdx.x;
    int d = blockIdx.x*128 + tid;
    int c = blockIdx.y;
    int vb = blockIdx.z;
    int chain = vb >> 1;
    int row0 = vb*LL + c*CH;
    const float* Al  = chain ? Al1  : Al0;
    const float* Wdt = chain ? Wdt1 : Wdt0;
    float bdt = (chain ? bdt1 : bdt0)[d];

    for (int i = tid; i < CH*DS; i += 128) {
        int l = i >> 4, s = i & 15;
        Bsm[l][s] = g_dbl[(row0 + l)*48 + DR + s];
        Dsm[l][s] = g_dbl[(row0 + l)*48 + s];
    }
    __syncthreads();

    float Aa[DS], h[DS], P[DS], Wr[DR];
#pragma unroll
    for (int s = 0; s < DS; s++) {
        Aa[s] = -__expf(Al[d*DS + s]);
        h[s] = 0.f; P[s] = 1.f;
    }
#pragma unroll
    for (int j = 0; j < DR; j++) Wr[j] = Wdt[d*DR + j];

    for (int l = 0; l < CH; l++) {
        int row = row0 + l;
        float a0 = bdt;
#pragma unroll
        for (int j = 0; j < DR; j++) a0 = fmaf(Dsm[l][j], Wr[j], a0);
        float dt = (a0 > 20.f) ? a0 : log1pf(__expf(a0));
        g_dt[(size_t)row*DI + d] = dt;
        float xv = __bfloat162float(g_xc_hi[(size_t)row*DI + d])
                 + __bfloat162float(g_xc_lo[(size_t)row*DI + d]);
        float dtx = dt * xv;
#pragma unroll
        for (int s = 0; s < DS; s++) {
            float a = __expf(dt * Aa[s]);
            h[s] = fmaf(a, h[s], dtx * Bsm[l][s]);
            P[s] *= a;
        }
    }
    size_t base = ((size_t)(vb*DI + d)*NC + c)*DS;
#pragma unroll
    for (int s = 0; s < DS; s++) { g_P[base + s] = P[s]; g_H[base + s] = h[s]; }
}

// ---------------- scan pass 2: combine chunk states ----------------
__global__ void scan2_k()
{
    int idx = blockIdx.x*256 + threadIdx.x;   // VB*DI*DS = 32768
    int bd = idx >> 4, s = idx & 15;
    float h = 0.f;
#pragma unroll
    for (int c = 0; c < NC; c++) {
        size_t o = ((size_t)bd*NC + c)*DS + s;
        g_Hi[o] = h;
        h = fmaf(g_P[o], h, g_H[o]);
    }
}

// ---------------- scan pass 3: recompute with init + fused epilogue (split output) --------
__global__ __launch_bounds__(128)
void scan3_k(const float* __restrict__ Al0, const float* __restrict__ Al1,
             const float* __restrict__ Dp0, const float* __restrict__ Dp1)
{
    __shared__ float Bsm[CH][DS];
    __shared__ float Csm[CH][DS];
    int tid = threadIdx.x;
    int d = blockIdx.x*128 + tid;
    int c = blockIdx.y;
    int vb = blockIdx.z;
    int chain = vb >> 1;
    int row0 = vb*LL + c*CH;
    const float* Al = chain ? Al1 : Al0;
    float Dv = (chain ? Dp1 : Dp0)[d];

    for (int i = tid; i < CH*DS; i += 128) {
        int l = i >> 4, s = i & 15;
        Bsm[l][s] = g_dbl[(row0 + l)*48 + DR + s];
        Csm[l][s] = g_dbl[(row0 + l)*48 + DR + DS + s];
    }
    __syncthreads();

    float Aa[DS], h[DS];
    size_t base = ((size_t)(vb*DI + d)*NC + c)*DS;
#pragma unroll
    for (int s = 0; s < DS; s++) {
        Aa[s] = -__expf(Al[d*DS + s]);
        h[s] = g_Hi[base + s];
    }

    for (int l = 0; l < CH; l++) {
        int row = row0 + l;
        size_t o = (size_t)row*DI + d;
        float dt = g_dt[o];
        float xv = __bfloat162float(g_xc_hi[o]) + __bfloat162float(g_xc_lo[o]);
        float zv = g_xz[(size_t)row*(2*DI) + DI + d];
        float dtx = dt * xv;
        float y = 0.f;
#pragma unroll
        for (int s = 0; s < DS; s++) {
            float a = __expf(dt * Aa[s]);
            h[s] = fmaf(a, h[s], dtx * Bsm[l][s]);
            y = fmaf(h[s], Csm[l][s], y);
        }
        y = fmaf(xv, Dv, y);
        float sz = zv * __fdividef(1.f, 1.f + __expf(-zv));
        split2(y * sz, g_y_hi[o], g_y_lo[o]);
    }
}

// ---------------- host orchestration ----------------
extern "C" void kernel_launch(void* const* d_in, const int* in_sizes, int n_in,
                              void* d_out, int out_size)
{
    (void)in_sizes; (void)n_in; (void)out_size;
    const float* x       = (const float*)d_in[0];
    const float* in_proj = (const float*)d_in[1];
    const float* conv_w  = (const float*)d_in[2];
    const float* conv_b  = (const float*)d_in[3];
    const float* x_proj  = (const float*)d_in[4];
    const float* dt_proj = (const float*)d_in[5];
    const float* dt_bias = (const float*)d_in[6];
    const float* A_log   = (const float*)d_in[7];
    const float* Dvec    = (const float*)d_in[8];
    const float* out_proj= (const float*)d_in[9];
    float* out = (float*)d_out;

    float *pXZ;
    bf16 *pAh, *pAl, *pBh, *pBl, *pYh, *pYl;
    bf16 *pWih, *pWil, *pWxh, *pWxl, *pWoh, *pWol;
    cudaGetSymbolAddress((void**)&pXZ,  g_xz);
    cudaGetSymbolAddress((void**)&pAh,  g_a_hi);  cudaGetSymbolAddress((void**)&pAl,  g_a_lo);
    cudaGetSymbolAddress((void**)&pBh,  g_b_hi);  cudaGetSymbolAddress((void**)&pBl,  g_b_lo);
    cudaGetSymbolAddress((void**)&pYh,  g_y_hi);  cudaGetSymbolAddress((void**)&pYl,  g_y_lo);
    cudaGetSymbolAddress((void**)&pWih, g_wi_hi); cudaGetSymbolAddress((void**)&pWil, g_wi_lo);
    cudaGetSymbolAddress((void**)&pWxh, g_wx_hi); cudaGetSymbolAddress((void**)&pWxl, g_wx_lo);
    cudaGetSymbolAddress((void**)&pWoh, g_wo_hi); cudaGetSymbolAddress((void**)&pWol, g_wo_lo);

    // all weight splits + input prep in one launch
    init_k<<<(N_WI + N_WO + N_WX + N_PR)/256, 256>>>(x, in_proj, out_proj, x_proj);

    for (int sl = 0; sl < 2; sl++) {
        int i0 = sl, i1 = sl + 2;
        const float* cw0  = conv_w  + (size_t)i0 * DI * DCV;
        const float* cw1  = conv_w  + (size_t)i1 * DI * DCV;
        const float* cb0  = conv_b  + (size_t)i0 * DI;
        const float* cb1  = conv_b  + (size_t)i1 * DI;
        const float* Wdt0 = dt_proj + (size_t)i0 * DI * DR;
        const float* Wdt1 = dt_proj + (size_t)i1 * DI * DR;
        const float* bdt0 = dt_bias + (size_t)i0 * DI;
        const float* bdt1 = dt_bias + (size_t)i1 * DI;
        const float* Al0  = A_log   + (size_t)i0 * DI * DS;
        const float* Al1  = A_log   + (size_t)i1 * DI * DS;
        const float* Dp0  = Dvec    + (size_t)i0 * DI;
        const float* Dp1  = Dvec    + (size_t)i1 * DI;

        const bf16* Ah  = (sl == 0) ? pAh : pBh;
        const bf16* Al_ = (sl == 0) ? pAl : pBl;

        // in_proj: (4096,256)x(1024,256)^T -> g_xz fp32    grid 16x32 = 512
        gemm_mma<128,0><<<dim3((2*DI)/64, MR2/128), 256>>>(
            Ah, Al_,
            pWih + (size_t)i0*2*DI*DM, pWil + (size_t)i0*2*DI*DM,
            pWih + (size_t)i1*2*DI*DM, pWil + (size_t)i1*2*DI*DM,
            pXZ, nullptr, nullptr, DM, 2*DI, 2*DI);
        // x_proj with fused conv+silu+split -> g_dbl + g_xc   grid 1x128
        xproj_k<<<dim3(1, MR2/32), 256>>>(
            cw0, cw1, cb0, cb1,
            pWxh + (size_t)i0*NXP*DI, pWxl + (size_t)i0*NXP*DI,
            pWxh + (size_t)i1*NXP*DI, pWxl + (size_t)i1*NXP*DI);
        // scan
        scan1_k<<<dim3(DI/128, NC, VB), 128>>>(Al0, Al1, Wdt0, Wdt1, bdt0, bdt1);
        scan2_k<<<(VB*DI*DS)/256, 256>>>();
        scan3_k<<<dim3(DI/128, NC, VB), 128>>>(Al0, Al1, Dp0, Dp1);
        // out_proj: (4096,512)x(256,512)^T                 grid 4x32 = 128
        if (sl == 0) {
            gemm_mma<128,2><<<dim3(DM/64, MR2/128), 256>>>(
                pYh, pYl,
                pWoh + (size_t)i0*DM*DI, pWol + (size_t)i0*DM*DI,
                pWoh + (size_t)i1*DM*DI, pWol + (size_t)i1*DM*DI,
                nullptr, pBh, pBl, DI, DM, DM);
        } else {
            gemm_mma<128,1><<<dim3(DM/64, MR2/128), 256>>>(
                pYh, pYl,
                pWoh + (size_t)i0*DM*DI, pWol + (size_t)i0*DM*DI,
                pWoh + (size_t)i1*DM*DI, pWol + (size_t)i1*DM*DI,
                out, nullptr, nullptr, DI, 2*DM, DM);
        }
    }
}